// round 1
// baseline (speedup 1.0000x reference)
#include <cuda_runtime.h>
#include <cuda_bf16.h>

#define BSZ 8
#define CH  64
#define H   256
#define W   256
#define HW  (H*W)
#define EPS 1e-5f
#define SLOPE 0.01f
#define CROP 244

// ---------------- scratch (no allocs allowed) ----------------
__device__ float g_actA[BSZ*CH*HW];          // 134 MB
__device__ float g_actB[BSZ*CH*HW];          // 134 MB
__device__ float g_stats[8*BSZ*CH*2];        // per-layer (sum, sumsq) accumulators
__device__ float g_norm[8*BSZ*CH*2];         // per-layer (mean, rstd)
__device__ float g_loss_sb[169*BSZ];

// ---------------- zero the stat accumulators ----------------
__global__ void zero_stats_kernel() {
    for (int i = threadIdx.x; i < 8*BSZ*CH*2; i += blockDim.x)
        g_stats[i] = 0.f;
}

// ---------------- fused conv + (input IN+LReLU) + output stats ----------------
// block tile: 16 co x 16 h x 32 w, 256 threads, thread = 4co x 2h x 4w
__global__ __launch_bounds__(256, 2)
void conv_kernel(const float* __restrict__ in,
                 const float* __restrict__ wgt,    // [16*gridDim.y][cin][9]
                 const float* __restrict__ bias,   // [64]
                 const float* __restrict__ innorm, // [BSZ*cin*2] (mean,rstd) or nullptr
                 float* __restrict__ out,
                 float* __restrict__ statacc,      // [BSZ*64*2]
                 int cin)
{
    __shared__ float s_w[16*64*9];   // 36864 B
    __shared__ float s_in[18*34];    //  2448 B

    const int tid   = threadIdx.x;
    const int tileW = blockIdx.x & 7;    // W/32
    const int tileH = blockIdx.x >> 3;   // H/16
    const int co_base = blockIdx.y * 16;
    const int b = blockIdx.z;

    // preload this co-tile's weights for all cin
    const int nw = 16 * cin * 9;
    for (int g = tid; g < nw; g += 256) {
        int co_l = g / (cin * 9);
        int rem  = g - co_l * (cin * 9);
        int ci   = rem / 9;
        int t    = rem - ci * 9;
        s_w[(ci*16 + co_l)*9 + t] = wgt[((co_base + co_l)*cin + ci)*9 + t];
    }

    const int sp = tid & 63, cg = tid >> 6;
    const int ph = sp >> 3, pw = sp & 7;
    const int h0 = tileH*16 + ph*2;
    const int w0 = tileW*32 + pw*4;

    float acc[4][2][4];
    #pragma unroll
    for (int k = 0; k < 4; k++)
        #pragma unroll
        for (int i = 0; i < 2; i++)
            #pragma unroll
            for (int j = 0; j < 4; j++) acc[k][i][j] = 0.f;

    const float* inb = in + (size_t)b * cin * HW;
    const int hbase = tileH*16 - 1;
    const int wbase = tileW*32 - 1;

    for (int ci = 0; ci < cin; ci++) {
        __syncthreads();   // also protects s_w preload on first iter
        const float* p = inb + ci * HW;
        float mean = 0.f, rstd = 0.f;
        if (innorm) {
            mean = innorm[(b*cin + ci)*2];
            rstd = innorm[(b*cin + ci)*2 + 1];
        }
        for (int g = tid; g < 18*34; g += 256) {
            int r = g / 34;
            int c = g - r * 34;
            int gh = hbase + r; gh = gh < 0 ? 0 : (gh > H-1 ? H-1 : gh);
            int gw = wbase + c; gw = gw < 0 ? 0 : (gw > W-1 ? W-1 : gw);
            float v = p[gh*W + gw];
            if (innorm) {   // fold InstanceNorm + LeakyReLU into the load
                v = (v - mean) * rstd;
                v = v >= 0.f ? v : SLOPE * v;
            }
            s_in[g] = v;
        }
        __syncthreads();

        float rin[4][6];
        #pragma unroll
        for (int r = 0; r < 4; r++)
            #pragma unroll
            for (int c = 0; c < 6; c++)
                rin[r][c] = s_in[(ph*2 + r)*34 + pw*4 + c];

        const float* wrow = &s_w[(ci*16 + cg*4)*9];
        #pragma unroll
        for (int k = 0; k < 4; k++) {
            float wv[9];
            #pragma unroll
            for (int t = 0; t < 9; t++) wv[t] = wrow[k*9 + t];
            #pragma unroll
            for (int i = 0; i < 2; i++)
                #pragma unroll
                for (int j = 0; j < 4; j++) {
                    float a = acc[k][i][j];
                    a = fmaf(rin[i  ][j  ], wv[0], a);
                    a = fmaf(rin[i  ][j+1], wv[1], a);
                    a = fmaf(rin[i  ][j+2], wv[2], a);
                    a = fmaf(rin[i+1][j  ], wv[3], a);
                    a = fmaf(rin[i+1][j+1], wv[4], a);
                    a = fmaf(rin[i+1][j+2], wv[5], a);
                    a = fmaf(rin[i+2][j  ], wv[6], a);
                    a = fmaf(rin[i+2][j+1], wv[7], a);
                    a = fmaf(rin[i+2][j+2], wv[8], a);
                    acc[k][i][j] = a;
                }
        }
    }

    // epilogue: bias, store, per-(b,co) stats via warp reduce + atomics
    #pragma unroll
    for (int k = 0; k < 4; k++) {
        int co = co_base + cg*4 + k;
        float bv = bias[co];
        float s = 0.f, sq = 0.f;
        float* ob = out + (size_t)(b*CH + co) * HW;
        #pragma unroll
        for (int i = 0; i < 2; i++) {
            float4 v;
            v.x = acc[k][i][0] + bv;
            v.y = acc[k][i][1] + bv;
            v.z = acc[k][i][2] + bv;
            v.w = acc[k][i][3] + bv;
            *reinterpret_cast<float4*>(&ob[(h0 + i)*W + w0]) = v;
            s  += v.x + v.y + v.z + v.w;
            sq += v.x*v.x + v.y*v.y + v.z*v.z + v.w*v.w;
        }
        #pragma unroll
        for (int off = 16; off; off >>= 1) {
            s  += __shfl_down_sync(0xffffffffu, s,  off);
            sq += __shfl_down_sync(0xffffffffu, sq, off);
        }
        if ((tid & 31) == 0) {
            atomicAdd(&statacc[(b*CH + co)*2    ], s);
            atomicAdd(&statacc[(b*CH + co)*2 + 1], sq);
        }
    }
}

// ---------------- stats -> (mean, rstd) ----------------
__global__ void finalize_kernel(const float* __restrict__ acc, float* __restrict__ nrm) {
    int i = blockIdx.x * blockDim.x + threadIdx.x;
    if (i < BSZ*CH) {
        const float inv = 1.f / (float)HW;
        float m = acc[2*i] * inv;
        float v = acc[2*i + 1] * inv - m*m;
        nrm[2*i]     = m;
        nrm[2*i + 1] = rsqrtf(v + EPS);
    }
}

// ---------------- projection conv (64->1) + residual ----------------
__global__ __launch_bounds__(256)
void proj_kernel(const float* __restrict__ in, const float* __restrict__ innorm,
                 const float* __restrict__ wgt, const float* __restrict__ bias,
                 const float* __restrict__ xIn, float* __restrict__ out)
{
    __shared__ float s_w[64*9];
    __shared__ float s_in[18*18];
    const int tid = threadIdx.x;
    const int tileH = blockIdx.x >> 4, tileW = blockIdx.x & 15;
    const int b = blockIdx.z;

    for (int g = tid; g < 576; g += 256) s_w[g] = wgt[g];

    const int ph = tid >> 4, pw = tid & 15;
    const int h = tileH*16 + ph, w = tileW*16 + pw;
    const int hbase = tileH*16 - 1, wbase = tileW*16 - 1;
    const float* inb = in + (size_t)b * CH * HW;

    float acc = 0.f;
    for (int ci = 0; ci < CH; ci++) {
        __syncthreads();
        float mean = innorm[(b*CH + ci)*2];
        float rstd = innorm[(b*CH + ci)*2 + 1];
        const float* p = inb + ci * HW;
        for (int g = tid; g < 18*18; g += 256) {
            int r = g / 18, c = g - r*18;
            int gh = hbase + r; gh = gh < 0 ? 0 : (gh > H-1 ? H-1 : gh);
            int gw = wbase + c; gw = gw < 0 ? 0 : (gw > W-1 ? W-1 : gw);
            float v = p[gh*W + gw];
            v = (v - mean) * rstd;
            v = v >= 0.f ? v : SLOPE * v;
            s_in[g] = v;
        }
        __syncthreads();
        const float* wv = &s_w[ci*9];
        #pragma unroll
        for (int kh = 0; kh < 3; kh++)
            #pragma unroll
            for (int kw = 0; kw < 3; kw++)
                acc = fmaf(s_in[(ph + kh)*18 + pw + kw], wv[kh*3 + kw], acc);
    }
    int idx = b*HW + h*W + w;
    out[idx] = acc + bias[0] + xIn[idx];
}

// ---------------- shift-search loss: var(crop - target) per (s,b) ----------------
__global__ __launch_bounds__(256)
void loss_kernel(const float* __restrict__ hr, const float* __restrict__ tgt,
                 float* __restrict__ loss_sb)
{
    const int s = blockIdx.x, b = blockIdx.y;
    const int sy = s / 13, sx = s - sy*13;
    const float* hp = hr + (size_t)b * HW;
    const float* tp = tgt + (size_t)b * HW;
    const int tid = threadIdx.x;

    float sum = 0.f, sq = 0.f;
    if (tid < CROP) {
        for (int r = 0; r < CROP; r++) {
            float d = hp[(sy + r)*W + sx + tid] - tp[(6 + r)*W + 6 + tid];
            sum += d; sq += d*d;
        }
    }
    __shared__ float s1[256], s2[256];
    s1[tid] = sum; s2[tid] = sq;
    __syncthreads();
    for (int off = 128; off; off >>= 1) {
        if (tid < off) { s1[tid] += s1[tid + off]; s2[tid] += s2[tid + off]; }
        __syncthreads();
    }
    if (tid == 0) {
        const float invN = 1.f / (float)(CROP*CROP);
        float m = s1[0] * invN;
        loss_sb[s*BSZ + b] = s2[0] * invN - m*m;
    }
}

__global__ void loss_final_kernel(const float* __restrict__ loss_sb, float* __restrict__ out) {
    __shared__ float mn[BSZ];
    int t = threadIdx.x;
    if (t < BSZ) {
        float m = loss_sb[t];
        for (int s = 1; s < 169; s++) m = fminf(m, loss_sb[s*BSZ + t]);
        mn[t] = m;
    }
    __syncthreads();
    if (t == 0) {
        float a = 0.f;
        for (int b = 0; b < BSZ; b++) a += mn[b];
        out[0] = a * (1.f / BSZ);
    }
}

// ---------------- launch ----------------
extern "C" void kernel_launch(void* const* d_in, const int* in_sizes, int n_in,
                              void* d_out, int out_size)
{
    const float* xIn    = (const float*)d_in[0];
    const float* target = (const float*)d_in[1];
    const float* w0     = (const float*)d_in[2];
    const float* b0     = (const float*)d_in[3];
    const float* ws     = (const float*)d_in[4];
    const float* bs     = (const float*)d_in[5];
    const float* wp     = (const float*)d_in[6];
    const float* bp     = (const float*)d_in[7];
    float* out = (float*)d_out;

    float *actA, *actB, *stats, *nrm, *lsb;
    cudaGetSymbolAddress((void**)&actA,  g_actA);
    cudaGetSymbolAddress((void**)&actB,  g_actB);
    cudaGetSymbolAddress((void**)&stats, g_stats);
    cudaGetSymbolAddress((void**)&nrm,   g_norm);
    cudaGetSymbolAddress((void**)&lsb,   g_loss_sb);

    zero_stats_kernel<<<1, 256>>>();

    dim3 cgrid(128, 4, BSZ);   // 8 w-tiles * 16 h-tiles, 4 co-tiles, 8 batch

    // layer 0: 1 -> 64, raw input
    conv_kernel<<<cgrid, 256>>>(xIn, w0, b0, nullptr, actA, stats, 1);
    finalize_kernel<<<2, 256>>>(stats, nrm);

    const float* cur = actA;
    float* nxt = actB;
    for (int i = 0; i < 7; i++) {
        conv_kernel<<<cgrid, 256>>>(cur, ws + (size_t)i*64*64*9, bs + i*64,
                                    nrm + (size_t)i*BSZ*CH*2, nxt,
                                    stats + (size_t)(i+1)*BSZ*CH*2, 64);
        finalize_kernel<<<2, 256>>>(stats + (size_t)(i+1)*BSZ*CH*2,
                                    nrm   + (size_t)(i+1)*BSZ*CH*2);
        float* tmp = (float*)cur; cur = nxt; nxt = tmp;
    }
    // cur = trunk layer-7 output (raw), norm slot 7

    proj_kernel<<<dim3(256, 1, BSZ), 256>>>(cur, nrm + (size_t)7*BSZ*CH*2,
                                            wp, bp, xIn, out);
    loss_kernel<<<dim3(169, BSZ), 256>>>(out, target, lsb);
    loss_final_kernel<<<1, 32>>>(lsb, out + (out_size - 1));
}

// round 2
// speedup vs baseline: 1.8483x; 1.8483x over previous
#include <cuda_runtime.h>
#include <cuda_bf16.h>

#define BSZ 8
#define CH  64
#define H   256
#define W   256
#define HW  (H*W)
#define EPS 1e-5f
#define SLOPE 0.01f
#define CROP 244

typedef unsigned long long u64;

#define FMA2(d,a,b,c) asm("fma.rn.f32x2 %0, %1, %2, %3;" : "=l"(d) : "l"(a), "l"(b), "l"(c))
#define PACK2(d,lo,hi) asm("mov.b64 %0, {%1, %2};" : "=l"(d) : "f"(lo), "f"(hi))
#define UNPK2(lo,hi,d) asm("mov.b64 {%0, %1}, %2;" : "=f"(lo), "=f"(hi) : "l"(d))

// ---------------- scratch (no allocs allowed) ----------------
__device__ float g_actA[BSZ*CH*HW];          // 134 MB
__device__ float g_actB[BSZ*CH*HW];          // 134 MB
__device__ float g_stats[8*BSZ*CH*2];        // per-layer (sum, sumsq)
__device__ float g_norm[8*BSZ*CH*2];         // per-layer (mean, rstd)
__device__ float g_loss_sb[169*BSZ];

__global__ void zero_stats_kernel() {
    for (int i = threadIdx.x; i < 8*BSZ*CH*2; i += blockDim.x)
        g_stats[i] = 0.f;
}

// ---------------- fused conv: f32x2-packed, double-buffered ----------------
// block tile: 16 co x 16 h x 32 w, 256 threads, thread = 4co x 2h x 4w
// co packed in pairs -> 2 copair x 2h x 4w = 16 f32x2 accumulators
__global__ __launch_bounds__(256, 2)
void conv_kernel(const float* __restrict__ in,
                 const float* __restrict__ wgt,    // [16*gridDim.y][cin][9]
                 const float* __restrict__ bias,   // [64]
                 const float* __restrict__ innorm, // [BSZ*cin*2] or nullptr
                 float* __restrict__ out,
                 float* __restrict__ statacc,      // [BSZ*64*2]
                 int cin)
{
    __shared__ float s_w[64*9*16];     // [ci][tap][co_l]  36864 B
    __shared__ float s_in[2][18*36];   // padded stride 36, double buffered

    const int tid   = threadIdx.x;
    const int tileW = blockIdx.x & 7;
    const int tileH = blockIdx.x >> 3;
    const int co_base = blockIdx.y * 16;
    const int b = blockIdx.z;

    // weights -> s_w[(ci*9+t)*16 + co_l]
    const int nw = cin * 9 * 16;
    for (int g = tid; g < nw; g += 256) {
        int co_l = g & 15;
        int ct   = g >> 4;
        int ci   = ct / 9;
        int t    = ct - ci*9;
        s_w[g] = wgt[((co_base + co_l)*cin + ci)*9 + t];
    }

    const int sp = tid & 63, cg = tid >> 6;
    const int ph = sp >> 3, pw = sp & 7;
    const int h0 = tileH*16 + ph*2;
    const int w0 = tileW*32 + pw*4;
    const int hbase = tileH*16 - 1, wbase = tileW*32 - 1;

    // precompute cooperative fill offsets (<=3 per thread, clamp-padded)
    int srcO[3], dstO[3]; bool act[3];
    #pragma unroll
    for (int k = 0; k < 3; k++) {
        int g = tid + k*256;
        act[k] = (g < 612);           // 18*34 valid elements
        int gg = act[k] ? g : 0;
        int r = gg / 34, c = gg - r*34;
        int gh = hbase + r; gh = gh < 0 ? 0 : (gh > H-1 ? H-1 : gh);
        int gw = wbase + c; gw = gw < 0 ? 0 : (gw > W-1 ? W-1 : gw);
        srcO[k] = gh*W + gw;
        dstO[k] = r*36 + c;
    }

    const float* inb = in + (size_t)b * cin * HW;

    // prologue: tile 0 -> buf 0 (IN+LReLU folded into fill)
    {
        float mean = 0.f, rstd = 1.f;
        if (innorm) { mean = innorm[(b*cin)*2]; rstd = innorm[(b*cin)*2+1]; }
        #pragma unroll
        for (int k = 0; k < 3; k++) if (act[k]) {
            float v = inb[srcO[k]];
            if (innorm) { v = (v - mean) * rstd; v = v >= 0.f ? v : SLOPE * v; }
            s_in[0][dstO[k]] = v;
        }
    }
    __syncthreads();   // also covers s_w

    u64 acc[2][2][4];
    #pragma unroll
    for (int p = 0; p < 2; p++)
        #pragma unroll
        for (int i = 0; i < 2; i++)
            #pragma unroll
            for (int j = 0; j < 4; j++) acc[p][i][j] = 0ull;

    for (int ci = 0; ci < cin; ci++) {
        const int buf = ci & 1;
        const int cn = (ci + 1 < cin) ? ci + 1 : cin - 1;

        // prefetch next channel's tile into regs (latency hidden by FFMA2 below)
        float pre[3];
        float nmean = 0.f, nrstd = 1.f;
        {
            const float* pn = inb + (size_t)cn * HW;
            if (innorm) {
                nmean = innorm[(b*cin + cn)*2];
                nrstd = innorm[(b*cin + cn)*2 + 1];
            }
            #pragma unroll
            for (int k = 0; k < 3; k++) pre[k] = act[k] ? pn[srcO[k]] : 0.f;
        }

        // load input rows, make duplicate-packed operands
        u64 dup[4][6];
        #pragma unroll
        for (int r = 0; r < 4; r++) {
            const float* row = &s_in[buf][(ph*2 + r)*36 + pw*4];
            float4 v4 = *reinterpret_cast<const float4*>(row);
            float2 v2 = *reinterpret_cast<const float2*>(row + 4);
            PACK2(dup[r][0], v4.x, v4.x);
            PACK2(dup[r][1], v4.y, v4.y);
            PACK2(dup[r][2], v4.z, v4.z);
            PACK2(dup[r][3], v4.w, v4.w);
            PACK2(dup[r][4], v2.x, v2.x);
            PACK2(dup[r][5], v2.y, v2.y);
        }

        // 144 FFMA2: 2 co-pairs x 9 taps x (2h x 4w)
        const float* wrow = &s_w[ci*9*16 + cg*4];
        #pragma unroll
        for (int p = 0; p < 2; p++) {
            u64 wv[9];
            #pragma unroll
            for (int t = 0; t < 9; t++)
                wv[t] = *reinterpret_cast<const u64*>(&wrow[t*16 + p*2]);
            #pragma unroll
            for (int kh = 0; kh < 3; kh++)
                #pragma unroll
                for (int kw = 0; kw < 3; kw++)
                    #pragma unroll
                    for (int i = 0; i < 2; i++)
                        #pragma unroll
                        for (int j = 0; j < 4; j++)
                            FMA2(acc[p][i][j], dup[i+kh][j+kw], wv[kh*3+kw], acc[p][i][j]);
        }

        // commit prefetched tile to the other buffer
        #pragma unroll
        for (int k = 0; k < 3; k++) if (act[k]) {
            float v = pre[k];
            if (innorm) { v = (v - nmean) * nrstd; v = v >= 0.f ? v : SLOPE * v; }
            s_in[buf ^ 1][dstO[k]] = v;
        }
        __syncthreads();
    }

    // epilogue: unpack, bias, store, per-(b,co) stats
    #pragma unroll
    for (int p = 0; p < 2; p++) {
        const int co0 = co_base + cg*4 + 2*p;
        const float bv0 = bias[co0], bv1 = bias[co0 + 1];
        float* ob0 = out + (size_t)(b*CH + co0    ) * HW;
        float* ob1 = out + (size_t)(b*CH + co0 + 1) * HW;
        float s0 = 0.f, q0 = 0.f, s1 = 0.f, q1 = 0.f;
        #pragma unroll
        for (int i = 0; i < 2; i++) {
            float lo[4], hi[4];
            #pragma unroll
            for (int j = 0; j < 4; j++) {
                float l, h;
                UNPK2(l, h, acc[p][i][j]);
                lo[j] = l + bv0; hi[j] = h + bv1;
                s0 += lo[j]; q0 += lo[j]*lo[j];
                s1 += hi[j]; q1 += hi[j]*hi[j];
            }
            *reinterpret_cast<float4*>(&ob0[(h0+i)*W + w0]) = make_float4(lo[0],lo[1],lo[2],lo[3]);
            *reinterpret_cast<float4*>(&ob1[(h0+i)*W + w0]) = make_float4(hi[0],hi[1],hi[2],hi[3]);
        }
        #pragma unroll
        for (int off = 16; off; off >>= 1) {
            s0 += __shfl_down_sync(0xffffffffu, s0, off);
            q0 += __shfl_down_sync(0xffffffffu, q0, off);
            s1 += __shfl_down_sync(0xffffffffu, s1, off);
            q1 += __shfl_down_sync(0xffffffffu, q1, off);
        }
        if ((tid & 31) == 0) {
            atomicAdd(&statacc[(b*CH + co0)*2    ], s0);
            atomicAdd(&statacc[(b*CH + co0)*2 + 1], q0);
            atomicAdd(&statacc[(b*CH + co0+1)*2    ], s1);
            atomicAdd(&statacc[(b*CH + co0+1)*2 + 1], q1);
        }
    }
}

// ---------------- stats -> (mean, rstd) ----------------
__global__ void finalize_kernel(const float* __restrict__ acc, float* __restrict__ nrm) {
    int i = blockIdx.x * blockDim.x + threadIdx.x;
    if (i < BSZ*CH) {
        const float inv = 1.f / (float)HW;
        float m = acc[2*i] * inv;
        float v = acc[2*i + 1] * inv - m*m;
        nrm[2*i]     = m;
        nrm[2*i + 1] = rsqrtf(v + EPS);
    }
}

// ---------------- projection conv (64->1) + residual ----------------
__global__ __launch_bounds__(256)
void proj_kernel(const float* __restrict__ in, const float* __restrict__ innorm,
                 const float* __restrict__ wgt, const float* __restrict__ bias,
                 const float* __restrict__ xIn, float* __restrict__ out)
{
    __shared__ float s_w[64*9];
    __shared__ float s_in[18*18];
    const int tid = threadIdx.x;
    const int tileH = blockIdx.x >> 4, tileW = blockIdx.x & 15;
    const int b = blockIdx.z;

    for (int g = tid; g < 576; g += 256) s_w[g] = wgt[g];

    const int ph = tid >> 4, pw = tid & 15;
    const int h = tileH*16 + ph, w = tileW*16 + pw;
    const int hbase = tileH*16 - 1, wbase = tileW*16 - 1;
    const float* inb = in + (size_t)b * CH * HW;

    float acc = 0.f;
    for (int ci = 0; ci < CH; ci++) {
        __syncthreads();
        float mean = innorm[(b*CH + ci)*2];
        float rstd = innorm[(b*CH + ci)*2 + 1];
        const float* p = inb + ci * HW;
        for (int g = tid; g < 18*18; g += 256) {
            int r = g / 18, c = g - r*18;
            int gh = hbase + r; gh = gh < 0 ? 0 : (gh > H-1 ? H-1 : gh);
            int gw = wbase + c; gw = gw < 0 ? 0 : (gw > W-1 ? W-1 : gw);
            float v = p[gh*W + gw];
            v = (v - mean) * rstd;
            v = v >= 0.f ? v : SLOPE * v;
            s_in[g] = v;
        }
        __syncthreads();
        const float* wv = &s_w[ci*9];
        #pragma unroll
        for (int kh = 0; kh < 3; kh++)
            #pragma unroll
            for (int kw = 0; kw < 3; kw++)
                acc = fmaf(s_in[(ph + kh)*18 + pw + kw], wv[kh*3 + kw], acc);
    }
    int idx = b*HW + h*W + w;
    out[idx] = acc + bias[0] + xIn[idx];
}

// ---------------- shift-search loss ----------------
__global__ __launch_bounds__(256)
void loss_kernel(const float* __restrict__ hr, const float* __restrict__ tgt,
                 float* __restrict__ loss_sb)
{
    const int s = blockIdx.x, b = blockIdx.y;
    const int sy = s / 13, sx = s - sy*13;
    const float* hp = hr + (size_t)b * HW;
    const float* tp = tgt + (size_t)b * HW;
    const int tid = threadIdx.x;

    float sum = 0.f, sq = 0.f;
    if (tid < CROP) {
        for (int r = 0; r < CROP; r++) {
            float d = hp[(sy + r)*W + sx + tid] - tp[(6 + r)*W + 6 + tid];
            sum += d; sq += d*d;
        }
    }
    __shared__ float s1[256], s2[256];
    s1[tid] = sum; s2[tid] = sq;
    __syncthreads();
    for (int off = 128; off; off >>= 1) {
        if (tid < off) { s1[tid] += s1[tid + off]; s2[tid] += s2[tid + off]; }
        __syncthreads();
    }
    if (tid == 0) {
        const float invN = 1.f / (float)(CROP*CROP);
        float m = s1[0] * invN;
        loss_sb[s*BSZ + b] = s2[0] * invN - m*m;
    }
}

__global__ void loss_final_kernel(const float* __restrict__ loss_sb, float* __restrict__ out) {
    __shared__ float mn[BSZ];
    int t = threadIdx.x;
    if (t < BSZ) {
        float m = loss_sb[t];
        for (int s = 1; s < 169; s++) m = fminf(m, loss_sb[s*BSZ + t]);
        mn[t] = m;
    }
    __syncthreads();
    if (t == 0) {
        float a = 0.f;
        for (int b = 0; b < BSZ; b++) a += mn[b];
        out[0] = a * (1.f / BSZ);
    }
}

// ---------------- launch ----------------
extern "C" void kernel_launch(void* const* d_in, const int* in_sizes, int n_in,
                              void* d_out, int out_size)
{
    const float* xIn    = (const float*)d_in[0];
    const float* target = (const float*)d_in[1];
    const float* w0     = (const float*)d_in[2];
    const float* b0     = (const float*)d_in[3];
    const float* ws     = (const float*)d_in[4];
    const float* bs     = (const float*)d_in[5];
    const float* wp     = (const float*)d_in[6];
    const float* bp     = (const float*)d_in[7];
    float* out = (float*)d_out;

    float *actA, *actB, *stats, *nrm, *lsb;
    cudaGetSymbolAddress((void**)&actA,  g_actA);
    cudaGetSymbolAddress((void**)&actB,  g_actB);
    cudaGetSymbolAddress((void**)&stats, g_stats);
    cudaGetSymbolAddress((void**)&nrm,   g_norm);
    cudaGetSymbolAddress((void**)&lsb,   g_loss_sb);

    zero_stats_kernel<<<1, 256>>>();

    dim3 cgrid(128, 4, BSZ);

    conv_kernel<<<cgrid, 256>>>(xIn, w0, b0, nullptr, actA, stats, 1);
    finalize_kernel<<<2, 256>>>(stats, nrm);

    const float* cur = actA;
    float* nxt = actB;
    for (int i = 0; i < 7; i++) {
        conv_kernel<<<cgrid, 256>>>(cur, ws + (size_t)i*64*64*9, bs + i*64,
                                    nrm + (size_t)i*BSZ*CH*2, nxt,
                                    stats + (size_t)(i+1)*BSZ*CH*2, 64);
        finalize_kernel<<<2, 256>>>(stats + (size_t)(i+1)*BSZ*CH*2,
                                    nrm   + (size_t)(i+1)*BSZ*CH*2);
        float* tmp = (float*)cur; cur = nxt; nxt = tmp;
    }

    proj_kernel<<<dim3(256, 1, BSZ), 256>>>(cur, nrm + (size_t)7*BSZ*CH*2,
                                            wp, bp, xIn, out);
    loss_kernel<<<dim3(169, BSZ), 256>>>(out, target, lsb);
    loss_final_kernel<<<1, 32>>>(lsb, out + (out_size - 1));
}